// round 11
// baseline (speedup 1.0000x reference)
#include <cuda_runtime.h>
#include <math.h>

// Problem constants (fixed by the reference)
#define B_DIM 2
#define L_DIM 2048
#define V_DIM 32001
#define ROWS (B_DIM * L_DIM)                       // 4096
#define ROW_BYTES ((long long)V_DIM * 4)           // 128004
#define REV_FLOATS (131076096LL)                   // ROWS * V_DIM, divisible by 8
#define N8 (REV_FLOATS / 8)                        // 16384512 32-byte units

// Persistent single-wave launch: 148 SMs x 8 blocks = 1184 CTAs total.
#define G_LOGIC 16                                 // logic blocks (4096 threads)
#define G_FILL 1168                                // fill blocks
#define G_TOTAL (G_LOGIC + G_FILL)                 // 1184 = one full wave
// Per-block contiguous region in 32B units, multiple of 4 (=128B) so every
// region starts line-aligned. 1168 * 14028 = 16384704 >= N8 (last block clamps).
#define FILL_CHUNK 14028LL

struct alignas(32) F8 { float4 a, b; };

__device__ __forceinline__ float gumbel_noise(float u) {
    const float GEPS = 1e-6f;
    return GEPS - logf(GEPS + (1.0f - GEPS) * u);
}

__device__ __forceinline__ bool is_mask_tok(int x) {
    return x == -1 || x == (V_DIM - 1);
}

// Single launch, single wave, no cross-block protocol:
//   blocks [0, G_LOGIC): row logic. x_new for every row; masked rows get the
//     full SEDD reverse-rate + gumbel sample, INCLUDING direct rev-row writes.
//   blocks [G_LOGIC, G_TOTAL): flat, 128B-aligned zero fill of rev, SKIPPING
//     bytes of masked rows. Each ~449KB region overlaps <=5 rows; <=5 xt loads
//     decide; with ~0 masked rows the fast path runs always.
__global__ __launch_bounds__(256, 8)
void fused_kernel(const float* __restrict__ outp,   // [B,L,V]
                  const int* __restrict__ xt,       // [B,L]
                  const float* __restrict__ t,      // [B]
                  const float* __restrict__ step_p, // [1]
                  const float* __restrict__ u,      // [B,L,V]
                  float* __restrict__ x_new,        // [B*L]
                  float* __restrict__ rev)          // [B,L,V]
{
    const int tid = threadIdx.x;
    const int mask_tok = V_DIM - 1;
    const float EPS = 1e-3f;

    if (blockIdx.x >= G_LOGIC) {
        // ---- fill path: one contiguous 128B-aligned region per block ----
        const long long fb = blockIdx.x - G_LOGIC;
        const long long base = fb * FILL_CHUNK;
        long long end = base + FILL_CHUNK;
        if (end > N8) end = N8;
        if (base >= end) return;

        const long long byte0 = base * 32;
        const long long byte1 = end * 32;
        const int row0 = (int)(byte0 / ROW_BYTES);
        int row1 = (int)((byte1 - 1) / ROW_BYTES);
        if (row1 > ROWS - 1) row1 = ROWS - 1;

        bool any_mask = false;
        for (int r = row0; r <= row1; r++)          // <=5 uniform loads
            any_mask |= is_mask_tok(xt[r]);

        if (!any_mask) {
            // fast path: contiguous 32B stores, every warp segment line-aligned
            F8 z; z.a = make_float4(0.f, 0.f, 0.f, 0.f); z.b = z.a;
            F8* __restrict__ p = (F8*)rev;
            for (long long i = base + tid; i < end; i += 256) p[i] = z;
        } else {
            // rare path: elementwise, skipping floats owned by masked rows
            // (floats never straddle rows: ROW_BYTES % 4 == 0)
            const long long f0 = byte0 >> 2, f1 = byte1 >> 2;
            for (long long i = f0 + tid; i < f1; i += 256) {
                const int r = (int)((i * 4) / ROW_BYTES);
                if (!is_mask_tok(xt[r])) rev[i] = 0.0f;
            }
        }
        return;
    }

    // ---- row logic: thread-per-row ----
    const int row = blockIdx.x * 256 + tid;   // 0..4095

    __shared__ int s_count;
    __shared__ int s_rows[256];
    if (tid == 0) s_count = 0;
    __syncthreads();

    int x = xt[row];
    if (x == -1) x = mask_tok;

    if (x != mask_tok) {
        // rev row is exactly zero; argmax of xt_prob/gnoise is x itself.
        x_new[row] = (float)x;
    } else {
        int slot = atomicAdd(&s_count, 1);
        s_rows[slot] = row;
    }
    __syncthreads();

    const int cnt = s_count;
    if (cnt == 0) return;

    // ---- cooperative heavy path: full rev row + gumbel sample ----
    __shared__ float s_sum[256];
    __shared__ float s_val[256];
    __shared__ int   s_idx[256];

    const float step = *step_p;

    for (int m = 0; m < cnt; m++) {
        const int mrow = s_rows[m];
        const int b = mrow / L_DIM;
        const float sigma = (1.0f - EPS) / (1.0f - (1.0f - EPS) * t[b]);

        const float* __restrict__ orow = outp + (long long)mrow * V_DIM;
        const float* __restrict__ urow = u    + (long long)mrow * V_DIM;
        float* __restrict__       rrow = rev  + (long long)mrow * V_DIM;

        float sum = 0.0f;
        float best_v = -INFINITY;
        int   best_i = V_DIM;

        for (int v = tid; v < V_DIM; v += 256) {
            if (v == mask_tok) continue;
            float s = expf(orow[v]);
            sum += s;
            float r = sigma * s;          // off-diagonal rev_rate
            rrow[v] = r;                  // fill skips this row -> no race
            float g = gumbel_noise(urow[v]);
            float ratio = (step * r) / g;
            if (ratio > best_v || (ratio == best_v && v < best_i)) {
                best_v = ratio;
                best_i = v;
            }
        }

        s_sum[tid] = sum;
        s_val[tid] = best_v;
        s_idx[tid] = best_i;
        __syncthreads();

        for (int off = 128; off > 0; off >>= 1) {
            if (tid < off) {
                s_sum[tid] += s_sum[tid + off];
                float ov = s_val[tid + off];
                int   oi = s_idx[tid + off];
                if (ov > s_val[tid] || (ov == s_val[tid] && oi < s_idx[tid])) {
                    s_val[tid] = ov;
                    s_idx[tid] = oi;
                }
            }
            __syncthreads();
        }

        if (tid == 0) {
            float rd = sigma * (-s_sum[0]);        // diagonal rev_rate
            rrow[mask_tok] = rd;
            float prob = 1.0f + step * rd;         // oh=1 at diagonal
            float g = gumbel_noise(urow[mask_tok]);
            float ratio = prob / g;
            int res = s_idx[0];
            if (ratio > s_val[0]) res = mask_tok;  // tie -> lower index wins
            x_new[mrow] = (res == mask_tok) ? -1.0f : (float)res;
        }
        __syncthreads();
    }
}

extern "C" void kernel_launch(void* const* d_in, const int* in_sizes, int n_in,
                              void* d_out, int out_size) {
    const float* outp   = (const float*)d_in[0]; // [B,L,V] f32
    const int*   xt     = (const int*)  d_in[1]; // [B,L]   i32
    const float* t      = (const float*)d_in[2]; // [B]     f32
    const float* step_p = (const float*)d_in[3]; // scalar  f32
    const float* u      = (const float*)d_in[4]; // [B,L,V] f32

    float* x_new = (float*)d_out;                  // first B*L elements
    float* rev   = (float*)d_out + ROWS;           // then B*L*V elements

    fused_kernel<<<G_TOTAL, 256>>>(outp, xt, t, step_p, u, x_new, rev);
}

// round 12
// speedup vs baseline: 1.1128x; 1.1128x over previous
#include <cuda_runtime.h>
#include <math.h>
#include <stdint.h>

// Problem constants (fixed by the reference)
#define B_DIM 2
#define L_DIM 2048
#define V_DIM 32001
#define ROWS (B_DIM * L_DIM)                       // 4096
#define ROW_BYTES ((long long)V_DIM * 4)           // 128004
#define REV_BYTES (524304384LL)                    // ROWS*V_DIM*4
#define CHUNK_BYTES 128128LL                       // per fill block, 128B-aligned
#define TMA_PIECE 16016                            // 8 pieces per chunk, mult of 16

#define G_LOGIC 16                                 // logic blocks (4096 threads)
#define G_FILL 4096                                // fill blocks
#define G_TOTAL (G_LOGIC + G_FILL)

#define TILE_BYTES 16384                           // zeroed SMEM source tile

__device__ __forceinline__ float gumbel_noise(float u) {
    const float GEPS = 1e-6f;
    return GEPS - logf(GEPS + (1.0f - GEPS) * u);
}

__device__ __forceinline__ bool is_mask_tok(int x) {
    return x == -1 || x == (V_DIM - 1);
}

// Single launch, no cross-block protocol:
//   blocks [0, G_LOGIC): row logic (x_new all rows; masked rows get full
//     rev-row + gumbel sample written directly).
//   blocks [G_LOGIC, G_TOTAL): zero-fill of rev via TMA bulk stores from a
//     zeroed SMEM tile, SKIPPING bytes of masked rows (chunk spans <=3 rows;
//     <=3 uniform xt loads decide; fast path taken essentially always).
__global__ __launch_bounds__(256, 8)
void fused_kernel(const float* __restrict__ outp,   // [B,L,V]
                  const int* __restrict__ xt,       // [B,L]
                  const float* __restrict__ t,      // [B]
                  const float* __restrict__ step_p, // [1]
                  const float* __restrict__ u,      // [B,L,V]
                  float* __restrict__ x_new,        // [B*L]
                  float* __restrict__ rev)          // [B,L,V]
{
    const int tid = threadIdx.x;
    const int mask_tok = V_DIM - 1;
    const float EPS = 1e-3f;

    // One 16KB buffer; fill path uses it as the TMA source tile, logic path
    // overlays its reduction arrays into it (a block runs exactly one path).
    __shared__ alignas(128) unsigned char s_tile[TILE_BYTES];
    __shared__ int s_count;

    if (blockIdx.x >= G_LOGIC) {
        // ---- fill path ----
        const long long fb = blockIdx.x - G_LOGIC;
        const long long byte0 = fb * CHUNK_BYTES;
        if (byte0 >= REV_BYTES) return;
        long long byte1 = byte0 + CHUNK_BYTES;
        if (byte1 > REV_BYTES) byte1 = REV_BYTES;

        const int row0 = (int)(byte0 / ROW_BYTES);
        int row1 = (int)((byte1 - 1) / ROW_BYTES);
        if (row1 > ROWS - 1) row1 = ROWS - 1;

        bool any_mask = false;
        for (int r = row0; r <= row1; r++)          // <=3 uniform loads
            any_mask |= is_mask_tok(xt[r]);

        if (!any_mask) {
            // zero the SMEM source tile
            float4* tp = (float4*)s_tile;
            const float4 z4 = make_float4(0.f, 0.f, 0.f, 0.f);
            for (int i = tid; i < TILE_BYTES / 16; i += 256) tp[i] = z4;
            __syncthreads();
            asm volatile("fence.proxy.async.shared::cta;" ::: "memory");

            if (tid == 0) {
                uint32_t saddr = (uint32_t)__cvta_generic_to_shared(s_tile);
                char* gbase = (char*)rev + byte0;
                long long total = byte1 - byte0;
                for (long long o = 0; o < total; o += TMA_PIECE) {
                    int sz = (int)((total - o < TMA_PIECE) ? (total - o)
                                                           : TMA_PIECE);
                    asm volatile(
                        "cp.async.bulk.global.shared::cta.bulk_group "
                        "[%0], [%1], %2;"
                        :: "l"(gbase + o), "r"(saddr), "r"(sz) : "memory");
                }
                asm volatile("cp.async.bulk.commit_group;" ::: "memory");
                asm volatile("cp.async.bulk.wait_group 0;" ::: "memory");
            }
            __syncthreads();   // keep s_tile alive until stores complete
        } else {
            // rare path: elementwise zero, skipping masked-row floats
            const long long f0 = byte0 >> 2, f1 = byte1 >> 2;
            for (long long i = f0 + tid; i < f1; i += 256) {
                const int r = (int)((i * 4) / ROW_BYTES);
                if (!is_mask_tok(xt[r])) rev[i] = 0.0f;
            }
        }
        return;
    }

    // ---- row logic: thread-per-row ----
    const int row = blockIdx.x * 256 + tid;   // 0..4095

    int*   s_rows = (int*)  (s_tile);          // 256 ints
    float* s_sum  = (float*)(s_tile + 1024);   // 256 floats
    float* s_val  = (float*)(s_tile + 2048);   // 256 floats
    int*   s_idx  = (int*)  (s_tile + 3072);   // 256 ints

    if (tid == 0) s_count = 0;
    __syncthreads();

    int x = xt[row];
    if (x == -1) x = mask_tok;

    if (x != mask_tok) {
        // rev row is exactly zero; argmax of xt_prob/gnoise is x itself.
        x_new[row] = (float)x;
    } else {
        int slot = atomicAdd(&s_count, 1);
        s_rows[slot] = row;
    }
    __syncthreads();

    const int cnt = s_count;
    if (cnt == 0) return;

    // ---- cooperative heavy path: full rev row + gumbel sample ----
    const float step = *step_p;

    for (int m = 0; m < cnt; m++) {
        const int mrow = s_rows[m];
        const int b = mrow / L_DIM;
        const float sigma = (1.0f - EPS) / (1.0f - (1.0f - EPS) * t[b]);

        const float* __restrict__ orow = outp + (long long)mrow * V_DIM;
        const float* __restrict__ urow = u    + (long long)mrow * V_DIM;
        float* __restrict__       rrow = rev  + (long long)mrow * V_DIM;

        float sum = 0.0f;
        float best_v = -INFINITY;
        int   best_i = V_DIM;

        for (int v = tid; v < V_DIM; v += 256) {
            if (v == mask_tok) continue;
            float s = expf(orow[v]);
            sum += s;
            float r = sigma * s;          // off-diagonal rev_rate
            rrow[v] = r;                  // fill skips this row -> no race
            float g = gumbel_noise(urow[v]);
            float ratio = (step * r) / g;
            if (ratio > best_v || (ratio == best_v && v < best_i)) {
                best_v = ratio;
                best_i = v;
            }
        }

        s_sum[tid] = sum;
        s_val[tid] = best_v;
        s_idx[tid] = best_i;
        __syncthreads();

        for (int off = 128; off > 0; off >>= 1) {
            if (tid < off) {
                s_sum[tid] += s_sum[tid + off];
                float ov = s_val[tid + off];
                int   oi = s_idx[tid + off];
                if (ov > s_val[tid] || (ov == s_val[tid] && oi < s_idx[tid])) {
                    s_val[tid] = ov;
                    s_idx[tid] = oi;
                }
            }
            __syncthreads();
        }

        if (tid == 0) {
            float rd = sigma * (-s_sum[0]);        // diagonal rev_rate
            rrow[mask_tok] = rd;
            float prob = 1.0f + step * rd;         // oh=1 at diagonal
            float g = gumbel_noise(urow[mask_tok]);
            float ratio = prob / g;
            int res = s_idx[0];
            if (ratio > s_val[0]) res = mask_tok;  // tie -> lower index wins
            x_new[mrow] = (res == mask_tok) ? -1.0f : (float)res;
        }
        __syncthreads();
    }
}

extern "C" void kernel_launch(void* const* d_in, const int* in_sizes, int n_in,
                              void* d_out, int out_size) {
    const float* outp   = (const float*)d_in[0]; // [B,L,V] f32
    const int*   xt     = (const int*)  d_in[1]; // [B,L]   i32
    const float* t      = (const float*)d_in[2]; // [B]     f32
    const float* step_p = (const float*)d_in[3]; // scalar  f32
    const float* u      = (const float*)d_in[4]; // [B,L,V] f32

    float* x_new = (float*)d_out;                  // first B*L elements
    float* rev   = (float*)d_out + ROWS;           // then B*L*V elements

    fused_kernel<<<G_TOTAL, 256>>>(outp, xt, t, step_p, u, x_new, rev);
}

// round 13
// speedup vs baseline: 1.1632x; 1.0453x over previous
#include <cuda_runtime.h>
#include <math.h>

// Problem constants (fixed by the reference)
#define B_DIM 2
#define L_DIM 2048
#define V_DIM 32001
#define ROWS (B_DIM * L_DIM)          // 4096 = 16 blocks x 256 threads

__device__ __forceinline__ float gumbel_noise(float u) {
    const float GEPS = 1e-6f;
    return GEPS - logf(GEPS + (1.0f - GEPS) * u);
}

// Thread-per-row logic kernel, launched with PDL so it overlaps the memset:
//  - x_new fast path touches only the x_new region (disjoint from the memset's
//    rev region) -> safe to run concurrently with the fill.
//  - masked rows (~0 of 4096) write rev; those writes are gated behind
//    cudaGridDependencySynchronize(), i.e. ordered after the memset completes.
__global__ void row_logic_kernel(const float* __restrict__ outp,   // [B,L,V]
                                 const int* __restrict__ xt,       // [B,L]
                                 const float* __restrict__ t,      // [B]
                                 const float* __restrict__ step_p, // [1]
                                 const float* __restrict__ u,      // [B,L,V]
                                 float* __restrict__ x_new,        // [B*L]
                                 float* __restrict__ rev)          // [B,L,V]
{
    const int tid = threadIdx.x;
    const int row = blockIdx.x * blockDim.x + tid;   // 0..4095
    const int mask_tok = V_DIM - 1;

    __shared__ int s_count;
    __shared__ int s_rows[256];

    if (tid == 0) s_count = 0;
    __syncthreads();

    int x = xt[row];
    if (x == -1) x = mask_tok;

    if (x != mask_tok) {
        x_new[row] = (float)x;      // concurrent-safe: disjoint from rev
    } else {
        int slot = atomicAdd(&s_count, 1);
        s_rows[slot] = row;
    }
    __syncthreads();

    const int cnt = s_count;
    if (cnt == 0) return;           // common case: no dependency wait at all

    // Masked rows exist: wait for the memset (primary) to complete before
    // touching the rev region, then run the cooperative heavy path.
    cudaGridDependencySynchronize();

    __shared__ float s_sum[256];
    __shared__ float s_val[256];
    __shared__ int   s_idx[256];

    const float EPS  = 1e-3f;
    const float step = *step_p;

    for (int m = 0; m < cnt; m++) {
        const int mrow = s_rows[m];
        const int b = mrow / L_DIM;
        const float sigma = (1.0f - EPS) / (1.0f - (1.0f - EPS) * t[b]);

        const float* __restrict__ orow = outp + (long long)mrow * V_DIM;
        const float* __restrict__ urow = u    + (long long)mrow * V_DIM;
        float* __restrict__       rrow = rev  + (long long)mrow * V_DIM;

        float sum = 0.0f;
        float best_v = -INFINITY;
        int   best_i = V_DIM;   // larger than any real index

        for (int v = tid; v < V_DIM; v += 256) {
            if (v == mask_tok) continue;
            float s = expf(orow[v]);
            sum += s;
            float r = sigma * s;          // rev_rate off-diagonal
            rrow[v] = r;
            float g = gumbel_noise(urow[v]);
            float ratio = (step * r) / g; // xt_prob[v] = 0 + step*rev
            if (ratio > best_v || (ratio == best_v && v < best_i)) {
                best_v = ratio;
                best_i = v;
            }
        }

        s_sum[tid] = sum;
        s_val[tid] = best_v;
        s_idx[tid] = best_i;
        __syncthreads();

        for (int off = 128; off > 0; off >>= 1) {
            if (tid < off) {
                s_sum[tid] += s_sum[tid + off];
                float ov = s_val[tid + off];
                int   oi = s_idx[tid + off];
                if (ov > s_val[tid] || (ov == s_val[tid] && oi < s_idx[tid])) {
                    s_val[tid] = ov;
                    s_idx[tid] = oi;
                }
            }
            __syncthreads();
        }

        if (tid == 0) {
            float total = s_sum[0];
            float rd = sigma * (-total);           // diagonal rev_rate
            rrow[mask_tok] = rd;
            float prob = 1.0f + step * rd;         // oh=1 at diagonal
            float g = gumbel_noise(urow[mask_tok]);
            float ratio = prob / g;
            int res = s_idx[0];
            float bv = s_val[0];
            // diagonal index is V-1 (largest), so on a tie off-diagonal wins
            if (ratio > bv) res = mask_tok;
            x_new[mrow] = (res == mask_tok) ? -1.0f : (float)res;
        }
        __syncthreads();
    }
}

extern "C" void kernel_launch(void* const* d_in, const int* in_sizes, int n_in,
                              void* d_out, int out_size) {
    const float* outp   = (const float*)d_in[0]; // [B,L,V] f32
    const int*   xt     = (const int*)  d_in[1]; // [B,L]   i32
    const float* t      = (const float*)d_in[2]; // [B]     f32
    const float* step_p = (const float*)d_in[3]; // scalar  f32
    const float* u      = (const float*)d_in[4]; // [B,L,V] f32

    float* x_new = (float*)d_out;                  // first B*L elements
    float* rev   = (float*)d_out + ROWS;           // then B*L*V elements

    // Compulsory 524 MB zero of rev_rate at the HBM write ceiling (~7.4 TB/s);
    // the driver memset beats every hand-rolled fill tried (STG/TMA ~7.0-7.1).
    cudaMemsetAsync(rev, 0, (size_t)ROWS * V_DIM * sizeof(float));

    // PDL launch: logic kernel overlaps the memset. Its rev writes (masked
    // rows only) are gated behind cudaGridDependencySynchronize().
    cudaLaunchConfig_t cfg = {};
    cfg.gridDim  = dim3(ROWS / 256, 1, 1);
    cfg.blockDim = dim3(256, 1, 1);
    cfg.dynamicSmemBytes = 0;
    cfg.stream = 0;
    cudaLaunchAttribute attrs[1];
    attrs[0].id = cudaLaunchAttributeProgrammaticStreamSerialization;
    attrs[0].val.programmaticStreamSerializationAllowed = 1;
    cfg.attrs = attrs;
    cfg.numAttrs = 1;
    cudaLaunchKernelEx(&cfg, row_logic_kernel,
                       outp, xt, t, step_p, u, x_new, rev);
}